// round 12
// baseline (speedup 1.0000x reference)
#include <cuda_runtime.h>
#include <cuda_bf16.h>
#include <math.h>
#include <stdint.h>

#define VOCAB   32000
#define EMBED   300
#define HIDDEN  1024
#define BATCH   64
#define SEQLEN  512
#define GDIM    4096

#define NCTA2   128    // persistent CTAs for LSTM (all resident, 1/SM)
#define TPB2    512

// ---------------- device scratch ----------------
__device__ float          g_xz[(size_t)SEQLEN * BATCH * GDIM];        // [t][b][g]
__device__ __nv_bfloat16  g_hsplit[2][2 * 64 * 1024];                 // [buf][plane hi/lo][b*1024+k]
__device__ __nv_bfloat16  g_Rsplit[(size_t)NCTA2 * 32 * 2048];        // [cta][n][k] k<1024:Rhi else Rlo
__device__ unsigned       g_bar_count;
__device__ volatile unsigned g_bar_gen;

// ---------------- grid barrier (all NCTA2 CTAs resident) -----------------
__device__ __forceinline__ void grid_barrier() {
    __syncthreads();
    if (threadIdx.x == 0) {
        __threadfence();
        unsigned g = g_bar_gen;
        if (atomicAdd(&g_bar_count, 1u) == NCTA2 - 1u) {
            atomicExch(&g_bar_count, 0u);
            __threadfence();
            g_bar_gen = g + 1u;
        } else {
            while (g_bar_gen == g) { __nanosleep(32); }
        }
        __threadfence();
    }
    __syncthreads();
}

// bf16 mma.sync m16n8k16, fp32 accumulate
__device__ __forceinline__ void mma16816(float* d,
                                         uint32_t a0, uint32_t a1, uint32_t a2, uint32_t a3,
                                         uint32_t b0, uint32_t b1) {
    asm volatile("mma.sync.aligned.m16n8k16.row.col.f32.bf16.bf16.f32 "
        "{%0,%1,%2,%3}, {%4,%5,%6,%7}, {%8,%9}, {%0,%1,%2,%3};"
        : "+f"(d[0]), "+f"(d[1]), "+f"(d[2]), "+f"(d[3])
        : "r"(a0), "r"(a1), "r"(a2), "r"(a3), "r"(b0), "r"(b1));
}
__device__ __forceinline__ void ldsm4(uint32_t& r0, uint32_t& r1, uint32_t& r2, uint32_t& r3,
                                      uint32_t addr) {
    asm volatile("ldmatrix.sync.aligned.m8n8.x4.shared.b16 {%0,%1,%2,%3}, [%4];"
        : "=r"(r0), "=r"(r1), "=r"(r2), "=r"(r3) : "r"(addr));
}
__device__ __forceinline__ void cp16(uint32_t dst, const void* src) {
    asm volatile("cp.async.cg.shared.global [%0], [%1], 16;" :: "r"(dst), "l"(src));
}
#define CP_COMMIT() asm volatile("cp.async.commit_group;" ::: "memory")
#define CP_WAIT0()  asm volatile("cp.async.wait_group 0;" ::: "memory")

__device__ __forceinline__ uint32_t smem_to_u32(const void* p) {
    uint32_t a;
    asm("{ .reg .u64 t; cvta.to.shared.u64 t, %1; cvt.u32.u64 %0, t; }" : "=r"(a) : "l"(p));
    return a;
}

// =========================================================================
// Prologue: zero h-split buffers
// =========================================================================
__global__ void hinit_kernel() {
    uint4 z = make_uint4(0, 0, 0, 0);
    int n4 = 2 * 2 * 64 * 1024 / 8;
    for (int i = blockIdx.x * blockDim.x + threadIdx.x; i < n4; i += gridDim.x * blockDim.x)
        ((uint4*)g_hsplit)[i] = z;
}

// =========================================================================
// Prologue: split R into bf16 hi/lo, CTA-grouped [cta][n][k]
// n = gate*8 + jl -> global col = gate*1024 + cta*8 + jl
// =========================================================================
__global__ void rsplit_kernel(const float* __restrict__ Rm) {
    size_t i = (size_t)blockIdx.x * blockDim.x + threadIdx.x;
    if (i >= (size_t)NCTA2 * 32 * 2048) return;
    int k   = (int)(i & 2047);
    int n   = (int)((i >> 11) & 31);
    int cta = (int)(i >> 16);
    int col = (n >> 3) * 1024 + cta * 8 + (n & 7);
    int ks  = k & 1023;
    float x = Rm[(size_t)ks * GDIM + col];
    __nv_bfloat16 hi = __float2bfloat16(x);
    g_Rsplit[i] = (k < 1024) ? hi : __float2bfloat16(x - __bfloat162float(hi));
}

// =========================================================================
// Phase 1: xz = emb[seq] @ W + bias   (SIMT fp32, known-good)
// =========================================================================
__global__ void __launch_bounds__(256) xz_gemm_kernel(
    const float* __restrict__ emb, const float* __restrict__ W,
    const float* __restrict__ bias, const int* __restrict__ seq)
{
    __shared__ float As[32][64];
    __shared__ float Bs[32][64];
    __shared__ int   toks[64];

    const int tid = threadIdx.x;
    const int m0  = blockIdx.y * 64;
    const int n0  = blockIdx.x * 64;

    if (tid < 64) {
        int m = m0 + tid;
        toks[tid] = seq[(m & 63) * SEQLEN + (m >> 6)];
    }
    __syncthreads();

    const int tx4 = (tid & 15) * 4;
    const int ty4 = (tid >> 4) * 4;

    float acc[4][4];
    {
        float4 bv = *(const float4*)&bias[n0 + tx4];
        #pragma unroll
        for (int i = 0; i < 4; i++) {
            acc[i][0] = bv.x; acc[i][1] = bv.y; acc[i][2] = bv.z; acc[i][3] = bv.w;
        }
    }

    for (int k0 = 0; k0 < EMBED; k0 += 32) {
        #pragma unroll
        for (int pass = 0; pass < 2; pass++) {
            int r  = (tid >> 3) + pass * 32;
            int cc = (tid & 7) * 4;
            int kk = k0 + cc;
            float4 v = make_float4(0.f, 0.f, 0.f, 0.f);
            if (kk < EMBED)
                v = *(const float4*)&emb[(size_t)toks[r] * EMBED + kk];
            As[cc + 0][r] = v.x; As[cc + 1][r] = v.y;
            As[cc + 2][r] = v.z; As[cc + 3][r] = v.w;
        }
        #pragma unroll
        for (int pass = 0; pass < 2; pass++) {
            int r  = (tid >> 4) + pass * 16;
            int e  = k0 + r;
            int cc = (tid & 15) * 4;
            float4 v = make_float4(0.f, 0.f, 0.f, 0.f);
            if (e < EMBED)
                v = *(const float4*)&W[(size_t)e * GDIM + n0 + cc];
            *(float4*)&Bs[r][cc] = v;
        }
        __syncthreads();

        #pragma unroll
        for (int kk = 0; kk < 32; kk++) {
            float4 a = *(const float4*)&As[kk][ty4];
            float4 b = *(const float4*)&Bs[kk][tx4];
            acc[0][0] += a.x*b.x; acc[0][1] += a.x*b.y; acc[0][2] += a.x*b.z; acc[0][3] += a.x*b.w;
            acc[1][0] += a.y*b.x; acc[1][1] += a.y*b.y; acc[1][2] += a.y*b.z; acc[1][3] += a.y*b.w;
            acc[2][0] += a.z*b.x; acc[2][1] += a.z*b.y; acc[2][2] += a.z*b.z; acc[2][3] += a.z*b.w;
            acc[3][0] += a.w*b.x; acc[3][1] += a.w*b.y; acc[3][2] += a.w*b.z; acc[3][3] += a.w*b.w;
        }
        __syncthreads();
    }

    #pragma unroll
    for (int i = 0; i < 4; i++) {
        float4 v = make_float4(acc[i][0], acc[i][1], acc[i][2], acc[i][3]);
        *(float4*)&g_xz[(size_t)(m0 + ty4 + i) * GDIM + n0 + tx4] = v;
    }
}

// =========================================================================
// Phase 2 v3: 512 threads / 16 warps, split-k warp pairing.
// Warps 0-7: 8 tiles (4m x 2n), k-slices 0-7 of each chunk; warps 8-15:
// same tiles, k-slices 8-15. Two z buffers summed in gate phase.
// Chunks 0-3: hi plane (vs Rhi AND Rlo); 4-7: lo plane (vs Rhi).
// =========================================================================
// smem layout (bytes)
#define SM_B     0         // 32 rows x 4112 B           = 131,584
#define BSTR_B   4112      // 2056 halves (pad 8)
#define SM_A     131584    // 2 bufs x 64 rows x 528 B   = 67,584
#define ABUF     33792
#define ASTR_B   528       // 264 halves (pad 8)
#define SM_Z     199168    // 2 x (64 x 33 floats)       = 16,896
#define SMEM2    216064

__global__ void __launch_bounds__(TPB2, 1)
lstm_mma_kernel(const int* __restrict__ seq, float* __restrict__ out)
{
    extern __shared__ char smem[];
    const uint32_t sb = smem_to_u32(smem);
    const int tid  = threadIdx.x;
    const int wid  = tid >> 5;
    const int lane = tid & 31;
    const int cta  = blockIdx.x;
    const int m0    = (wid & 3) * 16;
    const int nbase = ((wid >> 2) & 1) * 16;
    const int khalf = wid >> 3;          // 0: ks 0-7, 1: ks 8-15 of each chunk

    // ---- load resident B slice (32 x 2048 halves) ----
    {
        const uint4* src = (const uint4*)(g_Rsplit + (size_t)cta * 32 * 2048);
        for (int idx = tid; idx < 32 * 256; idx += TPB2) {
            int r = idx >> 8, c = idx & 255;
            *(uint4*)(smem + SM_B + r * BSTR_B + c * 16) = src[r * 256 + c];
        }
    }

    // gate ownership: one (b, j) element per thread
    const int gb = tid & 63;
    const int gj = tid >> 6;             // 0..7
    float c_r = 0.f, h_r = 0.f;

    // ldmatrix lane address components
    const int aRow = m0 + (lane & 7) + ((lane >> 3) & 1) * 8;
    const int aK8  = ((lane >> 4) & 1) * 8;
    const int bRow = nbase + (lane & 7) + ((lane >> 4) & 1) * 8;
    const int bK8  = ((lane >> 3) & 1) * 8;
    const uint32_t aAddr0 = sb + SM_A + aRow * ASTR_B + (khalf * 128 + aK8) * 2;
    const uint32_t bAddr0 = sb + SM_B + bRow * BSTR_B + bK8 * 2;

    float* z0_s = (float*)(smem + SM_Z);
    float* z1_s = (float*)(smem + SM_Z + 8448);
    float* zw_s = khalf ? z1_s : z0_s;

    grid_barrier();   // B_s loaded everywhere; h buffers zeroed by hinit

    int p = 0;
    for (int t = 0; t < SEQLEN; t++) {
        const __nv_bfloat16* hbase = g_hsplit[p];

        // prefetch gate inputs (hidden under the whole MMA phase)
        const float* xzr = g_xz + (size_t)t * (BATCH * GDIM) + (size_t)gb * GDIM + cta * 8 + gj;
        float xi = __ldcg(xzr);
        float xf = __ldcg(xzr + 1024);
        float xg = __ldcg(xzr + 2048);
        float xo = __ldcg(xzr + 3072);
        int   mv = __ldg(&seq[gb * SEQLEN + t]);

        float acc[8];
        #pragma unroll
        for (int i = 0; i < 8; i++) acc[i] = 0.f;

        // issue chunk 0 (hi plane, k0=0) -> buf 0
        #pragma unroll
        for (int i = 0; i < 4; i++) {
            int idx = i * TPB2 + tid;
            int r = idx >> 5, c = idx & 31;
            cp16(sb + SM_A + r * ASTR_B + c * 16, hbase + (size_t)r * 1024 + c * 8);
        }
        CP_COMMIT();

        for (int ci = 0; ci < 8; ci++) {
            CP_WAIT0();
            __syncthreads();
            if (ci < 7) {
                int cn = ci + 1;
                const __nv_bfloat16* pl = hbase + (cn < 4 ? 0 : 65536);
                int k0n = (cn & 3) * 256;
                #pragma unroll
                for (int i = 0; i < 4; i++) {
                    int idx = i * TPB2 + tid;
                    int r = idx >> 5, c = idx & 31;
                    cp16(sb + SM_A + (cn & 1) * ABUF + r * ASTR_B + c * 16,
                         pl + (size_t)r * 1024 + k0n + c * 8);
                }
                CP_COMMIT();
            }

            const uint32_t aB = aAddr0 + (ci & 1) * ABUF;
            const int k0 = (ci & 3) * 256 + khalf * 128;
            const bool isHi = (ci < 4);
            #pragma unroll
            for (int ks = 0; ks < 8; ks++) {
                const int kl = ks * 16;
                uint32_t a0, a1, a2, a3, b0, b1, b2, b3;
                ldsm4(a0, a1, a2, a3, aB + kl * 2);
                ldsm4(b0, b1, b2, b3, bAddr0 + (k0 + kl) * 2);
                mma16816(acc,     a0, a1, a2, a3, b0, b1);
                mma16816(acc + 4, a0, a1, a2, a3, b2, b3);
                if (isHi) {
                    ldsm4(b0, b1, b2, b3, bAddr0 + (1024 + k0 + kl) * 2);
                    mma16816(acc,     a0, a1, a2, a3, b0, b1);
                    mma16816(acc + 4, a0, a1, a2, a3, b2, b3);
                }
            }
        }

        // ---- park z tiles (one buffer per k-half) ----
        {
            const int fg = lane >> 2, ft = lane & 3;
            #pragma unroll
            for (int blk = 0; blk < 2; blk++) {
                int ncol = nbase + blk * 8 + 2 * ft;
                zw_s[(m0 + fg)     * 33 + ncol]     = acc[blk * 4 + 0];
                zw_s[(m0 + fg)     * 33 + ncol + 1] = acc[blk * 4 + 1];
                zw_s[(m0 + fg + 8) * 33 + ncol]     = acc[blk * 4 + 2];
                zw_s[(m0 + fg + 8) * 33 + ncol + 1] = acc[blk * 4 + 3];
            }
        }
        __syncthreads();

        // ---- gates: thread owns (b=gb, j = cta*8 + gj) ----
        {
            const bool msk = (mv != 0);
            const int  zb  = gb * 33 + gj;
            float zi = z0_s[zb]      + z1_s[zb]      + xi;
            float zf = z0_s[zb + 8]  + z1_s[zb + 8]  + xf;
            float zg = z0_s[zb + 16] + z1_s[zb + 16] + xg;
            float zo = z0_s[zb + 24] + z1_s[zb + 24] + xo;
            float ig  = 1.f / (1.f + expf(-zi));
            float fgt = 1.f / (1.f + expf(-zf));
            float gg  = tanhf(zg);
            float og  = 1.f / (1.f + expf(-zo));
            float cn = fgt * c_r + ig * gg;
            float hn = og * tanhf(cn);
            if (msk) { c_r = cn; h_r = hn; }

            __nv_bfloat16 hi = __float2bfloat16(h_r);
            __nv_bfloat16 lo = __float2bfloat16(h_r - __bfloat162float(hi));
            __nv_bfloat16* hN = g_hsplit[p ^ 1];
            hN[(size_t)gb * 1024 + cta * 8 + gj]         = hi;
            hN[65536 + (size_t)gb * 1024 + cta * 8 + gj] = lo;
        }

        p ^= 1;
        grid_barrier();
    }

    // final h -> out[b][1024]
    out[(size_t)gb * HIDDEN + cta * 8 + gj] = h_r;
}

// ---------------- launch ----------------
extern "C" void kernel_launch(void* const* d_in, const int* in_sizes, int n_in,
                              void* d_out, int out_size) {
    const float* emb  = nullptr;
    const float* W    = nullptr;
    const float* Rm   = nullptr;
    const float* bias = nullptr;
    const int*   seq  = nullptr;
    for (int i = 0; i < n_in; i++) {
        switch (in_sizes[i]) {
            case VOCAB * EMBED:  emb  = (const float*)d_in[i]; break;
            case EMBED * GDIM:   W    = (const float*)d_in[i]; break;
            case HIDDEN * GDIM:  Rm   = (const float*)d_in[i]; break;
            case GDIM:           bias = (const float*)d_in[i]; break;
            case BATCH * SEQLEN: seq  = (const int*)d_in[i];   break;
        }
    }
    (void)out_size;

    cudaFuncSetAttribute(lstm_mma_kernel, cudaFuncAttributeMaxDynamicSharedMemorySize, SMEM2);

    hinit_kernel<<<64, 256>>>();
    rsplit_kernel<<<(int)(((size_t)NCTA2 * 32 * 2048 + 255) / 256), 256>>>(Rm);
    dim3 g1(GDIM / 64, (SEQLEN * BATCH) / 64);
    xz_gemm_kernel<<<g1, 256>>>(emb, W, bias, seq);
    lstm_mma_kernel<<<NCTA2, TPB2, SMEM2>>>(seq, (float*)d_out);
}

// round 13
// speedup vs baseline: 1.2582x; 1.2582x over previous
#include <cuda_runtime.h>
#include <cuda_bf16.h>
#include <math.h>
#include <stdint.h>

#define VOCAB   32000
#define EMBED   300
#define HIDDEN  1024
#define BATCH   64
#define SEQLEN  512
#define GDIM    4096

#define NCTA2   128    // persistent CTAs for LSTM (all resident, 1/SM)
#define TPB2    512

// ---------------- device scratch ----------------
__device__ float          g_xz[(size_t)SEQLEN * BATCH * GDIM];        // [t][b][g]
__device__ __nv_bfloat16  g_hsplit[2][2 * 64 * 1024];                 // [buf][plane hi/lo][b*1024+k]
__device__ __nv_bfloat16  g_Rsplit[(size_t)NCTA2 * 32 * 2048];        // [cta][n][k] k<1024:Rhi else Rlo
__device__ unsigned       g_bar_count;
__device__ volatile unsigned g_bar_gen;

// ---------------- grid barrier (all NCTA2 CTAs resident) -----------------
__device__ __forceinline__ void grid_barrier() {
    __syncthreads();
    if (threadIdx.x == 0) {
        __threadfence();
        unsigned g = g_bar_gen;
        if (atomicAdd(&g_bar_count, 1u) == NCTA2 - 1u) {
            atomicExch(&g_bar_count, 0u);
            __threadfence();
            g_bar_gen = g + 1u;
        } else {
            while (g_bar_gen == g) { }
        }
        __threadfence();
    }
    __syncthreads();
}

// bf16 mma.sync m16n8k16, fp32 accumulate
__device__ __forceinline__ void mma16816(float* d,
                                         uint32_t a0, uint32_t a1, uint32_t a2, uint32_t a3,
                                         uint32_t b0, uint32_t b1) {
    asm volatile("mma.sync.aligned.m16n8k16.row.col.f32.bf16.bf16.f32 "
        "{%0,%1,%2,%3}, {%4,%5,%6,%7}, {%8,%9}, {%0,%1,%2,%3};"
        : "+f"(d[0]), "+f"(d[1]), "+f"(d[2]), "+f"(d[3])
        : "r"(a0), "r"(a1), "r"(a2), "r"(a3), "r"(b0), "r"(b1));
}
__device__ __forceinline__ void ldsm4(uint32_t& r0, uint32_t& r1, uint32_t& r2, uint32_t& r3,
                                      uint32_t addr) {
    asm volatile("ldmatrix.sync.aligned.m8n8.x4.shared.b16 {%0,%1,%2,%3}, [%4];"
        : "=r"(r0), "=r"(r1), "=r"(r2), "=r"(r3) : "r"(addr));
}
__device__ __forceinline__ void cp16(uint32_t dst, const void* src) {
    asm volatile("cp.async.cg.shared.global [%0], [%1], 16;" :: "r"(dst), "l"(src));
}
#define CP_COMMIT() asm volatile("cp.async.commit_group;" ::: "memory")
#define CP_WAIT0()  asm volatile("cp.async.wait_group 0;" ::: "memory")
#define NBAR(id)    asm volatile("bar.sync %0, 64;" :: "r"(id) : "memory")

__device__ __forceinline__ uint32_t smem_to_u32(const void* p) {
    uint32_t a;
    asm("{ .reg .u64 t; cvta.to.shared.u64 t, %1; cvt.u32.u64 %0, t; }" : "=r"(a) : "l"(p));
    return a;
}

// =========================================================================
// Prologue: zero h-split buffers
// =========================================================================
__global__ void hinit_kernel() {
    uint4 z = make_uint4(0, 0, 0, 0);
    int n4 = 2 * 2 * 64 * 1024 / 8;
    for (int i = blockIdx.x * blockDim.x + threadIdx.x; i < n4; i += gridDim.x * blockDim.x)
        ((uint4*)g_hsplit)[i] = z;
}

// =========================================================================
// Prologue: split R into bf16 hi/lo, CTA-grouped [cta][n][k]
// n = gate*8 + jl -> global col = gate*1024 + cta*8 + jl
// =========================================================================
__global__ void rsplit_kernel(const float* __restrict__ Rm) {
    size_t i = (size_t)blockIdx.x * blockDim.x + threadIdx.x;
    if (i >= (size_t)NCTA2 * 32 * 2048) return;
    int k   = (int)(i & 2047);
    int n   = (int)((i >> 11) & 31);
    int cta = (int)(i >> 16);
    int col = (n >> 3) * 1024 + cta * 8 + (n & 7);
    int ks  = k & 1023;
    float x = Rm[(size_t)ks * GDIM + col];
    __nv_bfloat16 hi = __float2bfloat16(x);
    g_Rsplit[i] = (k < 1024) ? hi : __float2bfloat16(x - __bfloat162float(hi));
}

// =========================================================================
// Phase 1: xz = emb[seq] @ W + bias   (SIMT fp32, known-good)
// =========================================================================
__global__ void __launch_bounds__(256) xz_gemm_kernel(
    const float* __restrict__ emb, const float* __restrict__ W,
    const float* __restrict__ bias, const int* __restrict__ seq)
{
    __shared__ float As[32][64];
    __shared__ float Bs[32][64];
    __shared__ int   toks[64];

    const int tid = threadIdx.x;
    const int m0  = blockIdx.y * 64;
    const int n0  = blockIdx.x * 64;

    if (tid < 64) {
        int m = m0 + tid;
        toks[tid] = seq[(m & 63) * SEQLEN + (m >> 6)];
    }
    __syncthreads();

    const int tx4 = (tid & 15) * 4;
    const int ty4 = (tid >> 4) * 4;

    float acc[4][4];
    {
        float4 bv = *(const float4*)&bias[n0 + tx4];
        #pragma unroll
        for (int i = 0; i < 4; i++) {
            acc[i][0] = bv.x; acc[i][1] = bv.y; acc[i][2] = bv.z; acc[i][3] = bv.w;
        }
    }

    for (int k0 = 0; k0 < EMBED; k0 += 32) {
        #pragma unroll
        for (int pass = 0; pass < 2; pass++) {
            int r  = (tid >> 3) + pass * 32;
            int cc = (tid & 7) * 4;
            int kk = k0 + cc;
            float4 v = make_float4(0.f, 0.f, 0.f, 0.f);
            if (kk < EMBED)
                v = *(const float4*)&emb[(size_t)toks[r] * EMBED + kk];
            As[cc + 0][r] = v.x; As[cc + 1][r] = v.y;
            As[cc + 2][r] = v.z; As[cc + 3][r] = v.w;
        }
        #pragma unroll
        for (int pass = 0; pass < 2; pass++) {
            int r  = (tid >> 4) + pass * 16;
            int e  = k0 + r;
            int cc = (tid & 15) * 4;
            float4 v = make_float4(0.f, 0.f, 0.f, 0.f);
            if (e < EMBED)
                v = *(const float4*)&W[(size_t)e * GDIM + n0 + cc];
            *(float4*)&Bs[r][cc] = v;
        }
        __syncthreads();

        #pragma unroll
        for (int kk = 0; kk < 32; kk++) {
            float4 a = *(const float4*)&As[kk][ty4];
            float4 b = *(const float4*)&Bs[kk][tx4];
            acc[0][0] += a.x*b.x; acc[0][1] += a.x*b.y; acc[0][2] += a.x*b.z; acc[0][3] += a.x*b.w;
            acc[1][0] += a.y*b.x; acc[1][1] += a.y*b.y; acc[1][2] += a.y*b.z; acc[1][3] += a.y*b.w;
            acc[2][0] += a.z*b.x; acc[2][1] += a.z*b.y; acc[2][2] += a.z*b.z; acc[2][3] += a.z*b.w;
            acc[3][0] += a.w*b.x; acc[3][1] += a.w*b.y; acc[3][2] += a.w*b.z; acc[3][3] += a.w*b.w;
        }
        __syncthreads();
    }

    #pragma unroll
    for (int i = 0; i < 4; i++) {
        float4 v = make_float4(acc[i][0], acc[i][1], acc[i][2], acc[i][3]);
        *(float4*)&g_xz[(size_t)(m0 + ty4 + i) * GDIM + n0 + tx4] = v;
    }
}

// =========================================================================
// Phase 2 v4: decoupled warp groups.
// 16 warps: m-tile = wid&3, n-tile = (wid>>2)&1, k-half = wid>>3.
// Group g = (wid&3) + khalf*4: the 2 warps sharing (m,khalf) stage a private
// 4KB A chunk double-buffer and sync only via named barrier 1+g.
// No CTA-wide syncs in the 8-chunk mainloop.
// =========================================================================
// smem layout (bytes)
#define SM_B     0          // 32 rows x 4112 B              = 131,584
#define BSTR_B   4112       // 2056 halves (pad 8)
#define SM_A     131584     // 8 grp x 2 buf x 4352 B        = 69,632
#define AGRP     8704
#define ABUFSZ   4352
#define ASTR_B   272        // 16 rows x (128+8 pad) halves
#define SM_Z     201216     // 2 x (64 x 33 floats)          = 16,896
#define SMEM2    218112

__global__ void __launch_bounds__(TPB2, 1)
lstm_mma_kernel(const int* __restrict__ seq, float* __restrict__ out)
{
    extern __shared__ char smem[];
    const uint32_t sb = smem_to_u32(smem);
    const int tid   = threadIdx.x;
    const int wid   = tid >> 5;
    const int lane  = tid & 31;
    const int cta   = blockIdx.x;
    const int mt    = wid & 3;
    const int ntile = (wid >> 2) & 1;
    const int khalf = wid >> 3;
    const int grp   = mt + khalf * 4;          // 0..7
    const int nbid  = 1 + grp;                 // named barrier id
    const int m0    = mt * 16;
    const int nbase = ntile * 16;

    // ---- load resident B slice (32 x 2048 halves) ----
    {
        const uint4* src = (const uint4*)(g_Rsplit + (size_t)cta * 32 * 2048);
        for (int idx = tid; idx < 32 * 256; idx += TPB2) {
            int r = idx >> 8, c = idx & 255;
            *(uint4*)(smem + SM_B + r * BSTR_B + c * 16) = src[r * 256 + c];
        }
    }

    // gate ownership: one (b, j) element per thread; coalesced mapping
    const int gb = tid >> 3;             // 0..63
    const int gj = tid & 7;              // 0..7
    float c_r = 0.f, h_r = 0.f;

    // ldmatrix lane address components (A rows are group-local 0..15)
    const int aRowL = (lane & 7) + ((lane >> 3) & 1) * 8;
    const int aK8   = ((lane >> 4) & 1) * 8;
    const int bRow  = nbase + (lane & 7) + ((lane >> 4) & 1) * 8;
    const int bK8   = ((lane >> 3) & 1) * 8;
    const uint32_t aAddr0 = sb + SM_A + grp * AGRP + aRowL * ASTR_B + aK8 * 2;
    const uint32_t bAddr0 = sb + SM_B + bRow * BSTR_B + bK8 * 2;
    const uint32_t aStage0 = sb + SM_A + grp * AGRP;

    float* z0_s = (float*)(smem + SM_Z);
    float* z1_s = (float*)(smem + SM_Z + 8448);
    float* zw_s = khalf ? z1_s : z0_s;

    grid_barrier();   // B_s loaded everywhere; h buffers zeroed by hinit

    int p = 0;
    for (int t = 0; t < SEQLEN; t++) {
        const __nv_bfloat16* hbase = g_hsplit[p];

        // prefetch gate inputs (hidden under the whole MMA phase)
        const float* xzr = g_xz + (size_t)t * (BATCH * GDIM) + (size_t)gb * GDIM + cta * 8 + gj;
        float xi = __ldcg(xzr);
        float xf = __ldcg(xzr + 1024);
        float xg = __ldcg(xzr + 2048);
        float xo = __ldcg(xzr + 3072);
        int   mv = __ldg(&seq[gb * SEQLEN + t]);

        float acc[8];
        #pragma unroll
        for (int i = 0; i < 8; i++) acc[i] = 0.f;

        // stage chunk 0 into buf 0 (group-private: rows m0..m0+15, my khalf)
        {
            const __nv_bfloat16* pl = hbase;   // chunk 0 = hi plane
            const int k0g = khalf * 128;
            #pragma unroll
            for (int pass = 0; pass < 4; pass++) {
                int u = pass * 64 + ntile * 32 + lane;
                int r = u >> 4, c = u & 15;
                cp16(aStage0 + r * ASTR_B + c * 16,
                     pl + (size_t)(m0 + r) * 1024 + k0g + c * 8);
            }
            CP_COMMIT();
        }

        for (int ci = 0; ci < 8; ci++) {
            CP_WAIT0();
            NBAR(nbid);           // both warps of the group see the chunk
            if (ci < 7) {
                int cn = ci + 1;
                const __nv_bfloat16* pl = hbase + (cn < 4 ? 0 : 65536);
                const int k0g = (cn & 3) * 256 + khalf * 128;
                const uint32_t dst = aStage0 + (cn & 1) * ABUFSZ;
                #pragma unroll
                for (int pass = 0; pass < 4; pass++) {
                    int u = pass * 64 + ntile * 32 + lane;
                    int r = u >> 4, c = u & 15;
                    cp16(dst + r * ASTR_B + c * 16,
                         pl + (size_t)(m0 + r) * 1024 + k0g + c * 8);
                }
                CP_COMMIT();
            }

            const uint32_t aB = aAddr0 + (ci & 1) * ABUFSZ;
            const int k0 = (ci & 3) * 256 + khalf * 128;
            const bool isHi = (ci < 4);
            #pragma unroll
            for (int ks = 0; ks < 8; ks++) {
                const int kl = ks * 16;
                uint32_t a0, a1, a2, a3, b0, b1, b2, b3;
                ldsm4(a0, a1, a2, a3, aB + kl * 2);
                ldsm4(b0, b1, b2, b3, bAddr0 + (k0 + kl) * 2);
                mma16816(acc,     a0, a1, a2, a3, b0, b1);
                mma16816(acc + 4, a0, a1, a2, a3, b2, b3);
                if (isHi) {
                    ldsm4(b0, b1, b2, b3, bAddr0 + (1024 + k0 + kl) * 2);
                    mma16816(acc,     a0, a1, a2, a3, b0, b1);
                    mma16816(acc + 4, a0, a1, a2, a3, b2, b3);
                }
            }
        }

        // ---- park z tiles (one buffer per k-half) ----
        {
            const int fg = lane >> 2, ft = lane & 3;
            #pragma unroll
            for (int blk = 0; blk < 2; blk++) {
                int ncol = nbase + blk * 8 + 2 * ft;
                zw_s[(m0 + fg)     * 33 + ncol]     = acc[blk * 4 + 0];
                zw_s[(m0 + fg)     * 33 + ncol + 1] = acc[blk * 4 + 1];
                zw_s[(m0 + fg + 8) * 33 + ncol]     = acc[blk * 4 + 2];
                zw_s[(m0 + fg + 8) * 33 + ncol + 1] = acc[blk * 4 + 3];
            }
        }
        __syncthreads();

        // ---- gates: thread owns (b=gb, j = cta*8 + gj) ----
        {
            const bool msk = (mv != 0);
            const int  zb  = gb * 33 + gj;
            float zi = z0_s[zb]      + z1_s[zb]      + xi;
            float zf = z0_s[zb + 8]  + z1_s[zb + 8]  + xf;
            float zg = z0_s[zb + 16] + z1_s[zb + 16] + xg;
            float zo = z0_s[zb + 24] + z1_s[zb + 24] + xo;
            float ig  = 1.f / (1.f + expf(-zi));
            float fgt = 1.f / (1.f + expf(-zf));
            float gg  = tanhf(zg);
            float og  = 1.f / (1.f + expf(-zo));
            float cn = fgt * c_r + ig * gg;
            float hn = og * tanhf(cn);
            if (msk) { c_r = cn; h_r = hn; }

            __nv_bfloat16 hi = __float2bfloat16(h_r);
            __nv_bfloat16 lo = __float2bfloat16(h_r - __bfloat162float(hi));
            __nv_bfloat16* hN = g_hsplit[p ^ 1];
            hN[(size_t)gb * 1024 + cta * 8 + gj]         = hi;
            hN[65536 + (size_t)gb * 1024 + cta * 8 + gj] = lo;
        }

        p ^= 1;
        grid_barrier();
    }

    // final h -> out[b][1024]
    out[(size_t)gb * HIDDEN + cta * 8 + gj] = h_r;
}

// ---------------- launch ----------------
extern "C" void kernel_launch(void* const* d_in, const int* in_sizes, int n_in,
                              void* d_out, int out_size) {
    const float* emb  = nullptr;
    const float* W    = nullptr;
    const float* Rm   = nullptr;
    const float* bias = nullptr;
    const int*   seq  = nullptr;
    for (int i = 0; i < n_in; i++) {
        switch (in_sizes[i]) {
            case VOCAB * EMBED:  emb  = (const float*)d_in[i]; break;
            case EMBED * GDIM:   W    = (const float*)d_in[i]; break;
            case HIDDEN * GDIM:  Rm   = (const float*)d_in[i]; break;
            case GDIM:           bias = (const float*)d_in[i]; break;
            case BATCH * SEQLEN: seq  = (const int*)d_in[i];   break;
        }
    }
    (void)out_size;

    cudaFuncSetAttribute(lstm_mma_kernel, cudaFuncAttributeMaxDynamicSharedMemorySize, SMEM2);

    hinit_kernel<<<64, 256>>>();
    rsplit_kernel<<<(int)(((size_t)NCTA2 * 32 * 2048 + 255) / 256), 256>>>(Rm);
    dim3 g1(GDIM / 64, (SEQLEN * BATCH) / 64);
    xz_gemm_kernel<<<g1, 256>>>(emb, W, bias, seq);
    lstm_mma_kernel<<<NCTA2, TPB2, SMEM2>>>(seq, (float*)d_out);
}

// round 14
// speedup vs baseline: 1.6006x; 1.2722x over previous
#include <cuda_runtime.h>
#include <cuda_bf16.h>
#include <math.h>
#include <stdint.h>

#define VOCAB   32000
#define EMBED   300
#define KPAD    304      // EMBED padded to multiple of 16
#define HIDDEN  1024
#define BATCH   64
#define SEQLEN  512
#define GDIM    4096

#define NCTA2   128    // persistent CTAs for LSTM (all resident, 1/SM)
#define TPB2    512

#define ESZ     (VOCAB * KPAD)     // per-plane elements of split emb
#define WSZ     (GDIM * KPAD)      // per-plane elements of split W (n-major)

// ---------------- device scratch ----------------
__device__ float          g_xz[(size_t)SEQLEN * BATCH * GDIM];        // [t][b][g]
__device__ __nv_bfloat16  g_esplit[2 * ESZ];                          // [plane][row][kpad]
__device__ __nv_bfloat16  g_wsplit[2 * WSZ];                          // [plane][n][kpad]
__device__ __nv_bfloat16  g_hsplit[2][2 * 64 * 1024];                 // [buf][plane hi/lo][b*1024+k]
__device__ __nv_bfloat16  g_Rsplit[(size_t)NCTA2 * 32 * 2048];        // [cta][n][k] k<1024:Rhi else Rlo
__device__ unsigned       g_bar_count;
__device__ volatile unsigned g_bar_gen;

// ---------------- grid barrier (all NCTA2 CTAs resident) -----------------
__device__ __forceinline__ void grid_barrier() {
    __syncthreads();
    if (threadIdx.x == 0) {
        __threadfence();
        unsigned g = g_bar_gen;
        if (atomicAdd(&g_bar_count, 1u) == NCTA2 - 1u) {
            atomicExch(&g_bar_count, 0u);
            __threadfence();
            g_bar_gen = g + 1u;
        } else {
            while (g_bar_gen == g) { }
        }
        __threadfence();
    }
    __syncthreads();
}

// bf16 mma.sync m16n8k16, fp32 accumulate
__device__ __forceinline__ void mma16816(float* d,
                                         uint32_t a0, uint32_t a1, uint32_t a2, uint32_t a3,
                                         uint32_t b0, uint32_t b1) {
    asm volatile("mma.sync.aligned.m16n8k16.row.col.f32.bf16.bf16.f32 "
        "{%0,%1,%2,%3}, {%4,%5,%6,%7}, {%8,%9}, {%0,%1,%2,%3};"
        : "+f"(d[0]), "+f"(d[1]), "+f"(d[2]), "+f"(d[3])
        : "r"(a0), "r"(a1), "r"(a2), "r"(a3), "r"(b0), "r"(b1));
}
__device__ __forceinline__ void ldsm4(uint32_t& r0, uint32_t& r1, uint32_t& r2, uint32_t& r3,
                                      uint32_t addr) {
    asm volatile("ldmatrix.sync.aligned.m8n8.x4.shared.b16 {%0,%1,%2,%3}, [%4];"
        : "=r"(r0), "=r"(r1), "=r"(r2), "=r"(r3) : "r"(addr));
}
__device__ __forceinline__ void cp16(uint32_t dst, const void* src) {
    asm volatile("cp.async.cg.shared.global [%0], [%1], 16;" :: "r"(dst), "l"(src));
}
#define CP_COMMIT() asm volatile("cp.async.commit_group;" ::: "memory")
#define CP_WAIT0()  asm volatile("cp.async.wait_group 0;" ::: "memory")
#define NBAR(id)    asm volatile("bar.sync %0, 64;" :: "r"(id) : "memory")

__device__ __forceinline__ uint32_t smem_to_u32(const void* p) {
    uint32_t a;
    asm("{ .reg .u64 t; cvta.to.shared.u64 t, %1; cvt.u32.u64 %0, t; }" : "=r"(a) : "l"(p));
    return a;
}

// =========================================================================
// Prologue: zero h-split buffers
// =========================================================================
__global__ void hinit_kernel() {
    uint4 z = make_uint4(0, 0, 0, 0);
    int n4 = 2 * 2 * 64 * 1024 / 8;
    for (int i = blockIdx.x * blockDim.x + threadIdx.x; i < n4; i += gridDim.x * blockDim.x)
        ((uint4*)g_hsplit)[i] = z;
}

// =========================================================================
// Prologue: split emb into bf16 hi/lo planes, K padded to 304
// =========================================================================
__global__ void esplit_kernel(const float* __restrict__ emb) {
    size_t i = (size_t)blockIdx.x * blockDim.x + threadIdx.x;
    if (i >= (size_t)ESZ) return;
    int k   = (int)(i % KPAD);
    int row = (int)(i / KPAD);
    float x = (k < EMBED) ? emb[(size_t)row * EMBED + k] : 0.f;
    __nv_bfloat16 hi = __float2bfloat16(x);
    g_esplit[i]       = hi;
    g_esplit[ESZ + i] = __float2bfloat16(x - __bfloat162float(hi));
}

// =========================================================================
// Prologue: split W into bf16 hi/lo planes, transposed to [n][kpad]
// =========================================================================
__global__ void wsplit_kernel(const float* __restrict__ W) {
    size_t i = (size_t)blockIdx.x * blockDim.x + threadIdx.x;
    if (i >= (size_t)WSZ) return;
    int k = (int)(i % KPAD);
    int n = (int)(i / KPAD);
    float x = (k < EMBED) ? W[(size_t)k * GDIM + n] : 0.f;
    __nv_bfloat16 hi = __float2bfloat16(x);
    g_wsplit[i]       = hi;
    g_wsplit[WSZ + i] = __float2bfloat16(x - __bfloat162float(hi));
}

// =========================================================================
// Prologue: split R into bf16 hi/lo, CTA-grouped [cta][n][k]
// =========================================================================
__global__ void rsplit_kernel(const float* __restrict__ Rm) {
    size_t i = (size_t)blockIdx.x * blockDim.x + threadIdx.x;
    if (i >= (size_t)NCTA2 * 32 * 2048) return;
    int k   = (int)(i & 2047);
    int n   = (int)((i >> 11) & 31);
    int cta = (int)(i >> 16);
    int col = (n >> 3) * 1024 + cta * 8 + (n & 7);
    int ks  = k & 1023;
    float x = Rm[(size_t)ks * GDIM + col];
    __nv_bfloat16 hi = __float2bfloat16(x);
    g_Rsplit[i] = (k < 1024) ? hi : __float2bfloat16(x - __bfloat162float(hi));
}

// =========================================================================
// Phase 1 (tensor-core): xz = emb[seq] @ W + bias
// M=32768 (m = t*64+b), K=304, N=4096. 3-term bf16 split.
// CTA tile 64m x 128n, 256 thr / 8 warps (warp m16 x n64), 19 k16-slices,
// cp.async double-buffered, ldmatrix frags, 48B row stride (conflict-free).
// =========================================================================
#define P1T     256
#define A_PL    (64 * 24)     // halves per A plane buffer (row stride 24 halves)
#define W_PL    (128 * 24)    // halves per W plane buffer

__global__ void __launch_bounds__(P1T) xz_mma_kernel(
    const float* __restrict__ bias, const int* __restrict__ seq)
{
    __shared__ __align__(16) __nv_bfloat16 Asm[2][2][A_PL];   // [buf][plane]
    __shared__ __align__(16) __nv_bfloat16 Wsm[2][2][W_PL];
    __shared__ int toks[64];

    const int tid  = threadIdx.x;
    const int wid  = tid >> 5;
    const int lane = tid & 31;
    const int n0   = blockIdx.x * 128;
    const int m0   = blockIdx.y * 64;
    const int mt   = wid & 3;            // m subtile (16 rows)
    const int ntw  = (wid >> 2) & 1;     // n subtile (64 cols)

    if (tid < 64) {
        int m = m0 + tid;
        toks[tid] = seq[(m & 63) * SEQLEN + (m >> 6)];
    }
    __syncthreads();

    const uint32_t sbA0 = smem_to_u32(&Asm[0][0][0]);
    const uint32_t sbW0 = smem_to_u32(&Wsm[0][0][0]);
    const uint32_t ABUF = 2 * A_PL * 2;  // bytes per A buffer (both planes)
    const uint32_t WBUF = 2 * W_PL * 2;

    // ldmatrix lane address components
    const int aRowL = (lane & 7) + ((lane >> 3) & 1) * 8;
    const int aK8   = ((lane >> 4) & 1) * 8;
    const int bRowL = (lane & 7) + ((lane >> 4) & 1) * 8;
    const int bK8   = ((lane >> 3) & 1) * 8;
    const uint32_t aBase = sbA0 + (mt * 16 + aRowL) * 48 + aK8 * 2;
    const uint32_t wBase = sbW0 + (ntw * 64 + bRowL) * 48 + bK8 * 2;

    float acc[4][8];
    #pragma unroll
    for (int q = 0; q < 4; q++)
        #pragma unroll
        for (int i = 0; i < 8; i++) acc[q][i] = 0.f;

    // ---- stage slice 0 into buf 0 ----
    {
        int u = tid;                          // A: 256 chunks
        int pl = u >> 7, r = (u >> 1) & 63, c = u & 1;
        cp16(sbA0 + pl * (A_PL * 2) + r * 48 + c * 16,
             g_esplit + (size_t)pl * ESZ + (size_t)toks[r] * KPAD + c * 8);
        #pragma unroll
        for (int pass = 0; pass < 2; pass++) {   // W: 512 chunks
            int v = pass * P1T + tid;
            int wpl = v >> 8, wr = (v >> 1) & 127, wc = v & 1;
            cp16(sbW0 + wpl * (W_PL * 2) + wr * 48 + wc * 16,
                 g_wsplit + (size_t)wpl * WSZ + (size_t)(n0 + wr) * KPAD + wc * 8);
        }
        CP_COMMIT();
    }

    for (int s = 0; s < 19; s++) {
        CP_WAIT0();
        __syncthreads();
        if (s < 18) {
            const int k0 = (s + 1) * 16;
            const uint32_t ab = sbA0 + ((s + 1) & 1) * ABUF;
            const uint32_t wb = sbW0 + ((s + 1) & 1) * WBUF;
            int u = tid;
            int pl = u >> 7, r = (u >> 1) & 63, c = u & 1;
            cp16(ab + pl * (A_PL * 2) + r * 48 + c * 16,
                 g_esplit + (size_t)pl * ESZ + (size_t)toks[r] * KPAD + k0 + c * 8);
            #pragma unroll
            for (int pass = 0; pass < 2; pass++) {
                int v = pass * P1T + tid;
                int wpl = v >> 8, wr = (v >> 1) & 127, wc = v & 1;
                cp16(wb + wpl * (W_PL * 2) + wr * 48 + wc * 16,
                     g_wsplit + (size_t)wpl * WSZ + (size_t)(n0 + wr) * KPAD + k0 + wc * 8);
            }
            CP_COMMIT();
        }

        const uint32_t aB = aBase + (s & 1) * ABUF;
        const uint32_t wB = wBase + (s & 1) * WBUF;
        uint32_t ah0, ah1, ah2, ah3, al0, al1, al2, al3;
        ldsm4(ah0, ah1, ah2, ah3, aB);                 // A hi
        ldsm4(al0, al1, al2, al3, aB + A_PL * 2);      // A lo
        #pragma unroll
        for (int q = 0; q < 4; q++) {
            uint32_t b0, b1, b2, b3;
            ldsm4(b0, b1, b2, b3, wB + q * 16 * 48);               // W hi, n16 subtile q
            mma16816(acc[q],     ah0, ah1, ah2, ah3, b0, b1);
            mma16816(acc[q] + 4, ah0, ah1, ah2, ah3, b2, b3);
            mma16816(acc[q],     al0, al1, al2, al3, b0, b1);
            mma16816(acc[q] + 4, al0, al1, al2, al3, b2, b3);
            ldsm4(b0, b1, b2, b3, wB + W_PL * 2 + q * 16 * 48);    // W lo
            mma16816(acc[q],     ah0, ah1, ah2, ah3, b0, b1);
            mma16816(acc[q] + 4, ah0, ah1, ah2, ah3, b2, b3);
        }
        __syncthreads();
    }

    // ---- epilogue: add bias, store fp32 ----
    {
        const int fg = lane >> 2, ft = lane & 3;
        const int row1 = m0 + mt * 16 + fg;
        #pragma unroll
        for (int q = 0; q < 4; q++) {
            #pragma unroll
            for (int pr = 0; pr < 2; pr++) {
                int col = n0 + ntw * 64 + q * 16 + pr * 8 + 2 * ft;
                float bx = __ldg(&bias[col]);
                float by = __ldg(&bias[col + 1]);
                *(float2*)&g_xz[(size_t)row1 * GDIM + col] =
                    make_float2(acc[q][pr * 4 + 0] + bx, acc[q][pr * 4 + 1] + by);
                *(float2*)&g_xz[(size_t)(row1 + 8) * GDIM + col] =
                    make_float2(acc[q][pr * 4 + 2] + bx, acc[q][pr * 4 + 3] + by);
            }
        }
    }
}

// =========================================================================
// Phase 2 v4 (unchanged R13 winner): decoupled warp groups.
// =========================================================================
// smem layout (bytes)
#define SM_B     0          // 32 rows x 4112 B              = 131,584
#define BSTR_B   4112       // 2056 halves (pad 8)
#define SM_A     131584     // 8 grp x 2 buf x 4352 B        = 69,632
#define AGRP     8704
#define ABUFSZ   4352
#define ASTR_B   272        // 16 rows x (128+8 pad) halves
#define SM_Z     201216     // 2 x (64 x 33 floats)          = 16,896
#define SMEM2    218112

__global__ void __launch_bounds__(TPB2, 1)
lstm_mma_kernel(const int* __restrict__ seq, float* __restrict__ out)
{
    extern __shared__ char smem[];
    const uint32_t sb = smem_to_u32(smem);
    const int tid   = threadIdx.x;
    const int wid   = tid >> 5;
    const int lane  = tid & 31;
    const int cta   = blockIdx.x;
    const int mt    = wid & 3;
    const int ntile = (wid >> 2) & 1;
    const int khalf = wid >> 3;
    const int grp   = mt + khalf * 4;          // 0..7
    const int nbid  = 1 + grp;                 // named barrier id
    const int m0    = mt * 16;
    const int nbase = ntile * 16;

    // ---- load resident B slice (32 x 2048 halves) ----
    {
        const uint4* src = (const uint4*)(g_Rsplit + (size_t)cta * 32 * 2048);
        for (int idx = tid; idx < 32 * 256; idx += TPB2) {
            int r = idx >> 8, c = idx & 255;
            *(uint4*)(smem + SM_B + r * BSTR_B + c * 16) = src[r * 256 + c];
        }
    }

    // gate ownership: one (b, j) element per thread; coalesced mapping
    const int gb = tid >> 3;             // 0..63
    const int gj = tid & 7;              // 0..7
    float c_r = 0.f, h_r = 0.f;

    // ldmatrix lane address components (A rows are group-local 0..15)
    const int aRowL = (lane & 7) + ((lane >> 3) & 1) * 8;
    const int aK8   = ((lane >> 4) & 1) * 8;
    const int bRow  = nbase + (lane & 7) + ((lane >> 4) & 1) * 8;
    const int bK8   = ((lane >> 3) & 1) * 8;
    const uint32_t aAddr0 = sb + SM_A + grp * AGRP + aRowL * ASTR_B + aK8 * 2;
    const uint32_t bAddr0 = sb + SM_B + bRow * BSTR_B + bK8 * 2;
    const uint32_t aStage0 = sb + SM_A + grp * AGRP;

    float* z0_s = (float*)(smem + SM_Z);
    float* z1_s = (float*)(smem + SM_Z + 8448);
    float* zw_s = khalf ? z1_s : z0_s;

    grid_barrier();   // B_s loaded everywhere; h buffers zeroed by hinit

    int p = 0;
    for (int t = 0; t < SEQLEN; t++) {
        const __nv_bfloat16* hbase = g_hsplit[p];

        // prefetch gate inputs (hidden under the whole MMA phase)
        const float* xzr = g_xz + (size_t)t * (BATCH * GDIM) + (size_t)gb * GDIM + cta * 8 + gj;
        float xi = __ldcg(xzr);
        float xf = __ldcg(xzr + 1024);
        float xg = __ldcg(xzr + 2048);
        float xo = __ldcg(xzr + 3072);
        int   mv = __ldg(&seq[gb * SEQLEN + t]);

        float acc[8];
        #pragma unroll
        for (int i = 0; i < 8; i++) acc[i] = 0.f;

        // stage chunk 0 into buf 0 (group-private: rows m0..m0+15, my khalf)
        {
            const __nv_bfloat16* pl = hbase;   // chunk 0 = hi plane
            const int k0g = khalf * 128;
            #pragma unroll
            for (int pass = 0; pass < 4; pass++) {
                int u = pass * 64 + ntile * 32 + lane;
                int r = u >> 4, c = u & 15;
                cp16(aStage0 + r * ASTR_B + c * 16,
                     pl + (size_t)(m0 + r) * 1024 + k0g + c * 8);
            }
            CP_COMMIT();
        }

        for (int ci = 0; ci < 8; ci++) {
            CP_WAIT0();
            NBAR(nbid);           // both warps of the group see the chunk
            if (ci < 7) {
                int cn = ci + 1;
                const __nv_bfloat16* pl = hbase + (cn < 4 ? 0 : 65536);
                const int k0g = (cn & 3) * 256 + khalf * 128;
                const uint32_t dst = aStage0 + (cn & 1) * ABUFSZ;
                #pragma unroll
                for (int pass = 0; pass < 4; pass++) {
                    int u = pass * 64 + ntile * 32 + lane;
                    int r = u >> 4, c = u & 15;
                    cp16(dst + r * ASTR_B + c * 16,
                         pl + (size_t)(m0 + r) * 1024 + k0g + c * 8);
                }
                CP_COMMIT();
            }

            const uint32_t aB = aAddr0 + (ci & 1) * ABUFSZ;
            const int k0 = (ci & 3) * 256 + khalf * 128;
            const bool isHi = (ci < 4);
            #pragma unroll
            for (int ks = 0; ks < 8; ks++) {
                const int kl = ks * 16;
                uint32_t a0, a1, a2, a3, b0, b1, b2, b3;
                ldsm4(a0, a1, a2, a3, aB + kl * 2);
                ldsm4(b0, b1, b2, b3, bAddr0 + (k0 + kl) * 2);
                mma16816(acc,     a0, a1, a2, a3, b0, b1);
                mma16816(acc + 4, a0, a1, a2, a3, b2, b3);
                if (isHi) {
                    ldsm4(b0, b1, b2, b3, bAddr0 + (1024 + k0 + kl) * 2);
                    mma16816(acc,     a0, a1, a2, a3, b0, b1);
                    mma16816(acc + 4, a0, a1, a2, a3, b2, b3);
                }
            }
        }

        // ---- park z tiles (one buffer per k-half) ----
        {
            const int fg = lane >> 2, ft = lane & 3;
            #pragma unroll
            for (int blk = 0; blk < 2; blk++) {
                int ncol = nbase + blk * 8 + 2 * ft;
                zw_s[(m0 + fg)     * 33 + ncol]     = acc[blk * 4 + 0];
                zw_s[(m0 + fg)     * 33 + ncol + 1] = acc[blk * 4 + 1];
                zw_s[(m0 + fg + 8) * 33 + ncol]     = acc[blk * 4 + 2];
                zw_s[(m0 + fg + 8) * 33 + ncol + 1] = acc[blk * 4 + 3];
            }
        }
        __syncthreads();

        // ---- gates: thread owns (b=gb, j = cta*8 + gj) ----
        {
            const bool msk = (mv != 0);
            const int  zb  = gb * 33 + gj;
            float zi = z0_s[zb]      + z1_s[zb]      + xi;
            float zf = z0_s[zb + 8]  + z1_s[zb + 8]  + xf;
            float zg = z0_s[zb + 16] + z1_s[zb + 16] + xg;
            float zo = z0_s[zb + 24] + z1_s[zb + 24] + xo;
            float ig  = 1.f / (1.f + expf(-zi));
            float fgt = 1.f / (1.f + expf(-zf));
            float gg  = tanhf(zg);
            float og  = 1.f / (1.f + expf(-zo));
            float cn = fgt * c_r + ig * gg;
            float hn = og * tanhf(cn);
            if (msk) { c_r = cn; h_r = hn; }

            __nv_bfloat16 hi = __float2bfloat16(h_r);
            __nv_bfloat16 lo = __float2bfloat16(h_r - __bfloat162float(hi));
            __nv_bfloat16* hN = g_hsplit[p ^ 1];
            hN[(size_t)gb * 1024 + cta * 8 + gj]         = hi;
            hN[65536 + (size_t)gb * 1024 + cta * 8 + gj] = lo;
        }

        p ^= 1;
        grid_barrier();
    }

    // final h -> out[b][1024]
    out[(size_t)gb * HIDDEN + cta * 8 + gj] = h_r;
}

// ---------------- launch ----------------
extern "C" void kernel_launch(void* const* d_in, const int* in_sizes, int n_in,
                              void* d_out, int out_size) {
    const float* emb  = nullptr;
    const float* W    = nullptr;
    const float* Rm   = nullptr;
    const float* bias = nullptr;
    const int*   seq  = nullptr;
    for (int i = 0; i < n_in; i++) {
        switch (in_sizes[i]) {
            case VOCAB * EMBED:  emb  = (const float*)d_in[i]; break;
            case EMBED * GDIM:   W    = (const float*)d_in[i]; break;
            case HIDDEN * GDIM:  Rm   = (const float*)d_in[i]; break;
            case GDIM:           bias = (const float*)d_in[i]; break;
            case BATCH * SEQLEN: seq  = (const int*)d_in[i];   break;
        }
    }
    (void)out_size;

    cudaFuncSetAttribute(lstm_mma_kernel, cudaFuncAttributeMaxDynamicSharedMemorySize, SMEM2);

    hinit_kernel<<<64, 256>>>();
    esplit_kernel<<<(int)(((size_t)ESZ + 255) / 256), 256>>>(emb);
    wsplit_kernel<<<(int)(((size_t)WSZ + 255) / 256), 256>>>(W);
    rsplit_kernel<<<(int)(((size_t)NCTA2 * 32 * 2048 + 255) / 256), 256>>>(Rm);
    dim3 g1(GDIM / 128, (SEQLEN * BATCH) / 64);   // (32, 512)
    xz_mma_kernel<<<g1, P1T>>>(bias, seq);
    lstm_mma_kernel<<<NCTA2, TPB2, SMEM2>>>(seq, (float*)d_out);
}